// round 16
// baseline (speedup 1.0000x reference)
#include <cuda_runtime.h>
#include <cuda_bf16.h>
#include <math.h>
#include <stdint.h>

// Problem constants
#define B_  2
#define L_  2048
#define H_  16
#define DK_ 64
#define D_  (H_ * DK_)        // 1024
#define ML_ (B_ * L_)         // 4096
#define KSPLIT2 4
#define KCH2 (L_ / KSPLIT2)   // 512

// Scratch (device globals: no allocation allowed)
__device__ float g_q[(size_t)ML_ * D_];
__device__ float g_k[(size_t)ML_ * D_];
__device__ float g_v[(size_t)ML_ * D_];
__device__ float g_attn[(size_t)ML_ * D_];
__device__ float g_rsum[(size_t)B_ * H_ * L_];
__device__ float2 g_rope[L_][32];
__device__ __nv_bfloat16 g_vh[B_ * H_][DK_][L_];   // V split hi, n-major
__device__ __nv_bfloat16 g_vl[B_ * H_][DK_][L_];   // V split lo, n-major
__device__ int   g_mask_kind;   // 0 = uint8, 1 = int32, 2 = float32

// ===========================================================================
// Helpers
// ===========================================================================
__device__ __forceinline__ uint32_t smem_u32(const void* p) {
    uint32_t a;
    asm("{ .reg .u64 t; cvta.to.shared.u64 t, %1; cvt.u32.u64 %0, t; }"
        : "=r"(a) : "l"(p));
    return a;
}

__device__ __forceinline__ void ldsm4(uint32_t* r, uint32_t addr) {
    asm volatile("ldmatrix.sync.aligned.m8n8.x4.shared.b16 {%0,%1,%2,%3}, [%4];"
                 : "=r"(r[0]), "=r"(r[1]), "=r"(r[2]), "=r"(r[3]) : "r"(addr));
}

__device__ __forceinline__ void mma16816(float* c, const uint32_t* a, const uint32_t* b) {
    asm volatile(
        "mma.sync.aligned.m16n8k16.row.col.f32.bf16.bf16.f32 "
        "{%0,%1,%2,%3}, {%4,%5,%6,%7}, {%8,%9}, {%0,%1,%2,%3};"
        : "+f"(c[0]), "+f"(c[1]), "+f"(c[2]), "+f"(c[3])
        : "r"(a[0]), "r"(a[1]), "r"(a[2]), "r"(a[3]), "r"(b[0]), "r"(b[1]));
}

__device__ __forceinline__ void red_add_v2(float* p, float a, float b) {
    asm volatile("red.global.add.v2.f32 [%0], {%1, %2};"
                 :: "l"(p), "f"(a), "f"(b) : "memory");
}

// Split fp32 float4 -> packed hi / lo bf16x2 pairs (uint2 each)
__device__ __forceinline__ void split4(float4 v, uint2& hi, uint2& lo) {
    __nv_bfloat16 h0 = __float2bfloat16(v.x), h1 = __float2bfloat16(v.y),
                  h2 = __float2bfloat16(v.z), h3 = __float2bfloat16(v.w);
    __nv_bfloat16 l0 = __float2bfloat16(v.x - __bfloat162float(h0)),
                  l1 = __float2bfloat16(v.y - __bfloat162float(h1)),
                  l2 = __float2bfloat16(v.z - __bfloat162float(h2)),
                  l3 = __float2bfloat16(v.w - __bfloat162float(h3));
    __nv_bfloat162 hp0 = __halves2bfloat162(h0, h1);
    __nv_bfloat162 hp1 = __halves2bfloat162(h2, h3);
    __nv_bfloat162 lp0 = __halves2bfloat162(l0, l1);
    __nv_bfloat162 lp1 = __halves2bfloat162(l2, l3);
    hi = make_uint2(*(uint32_t*)&hp0, *(uint32_t*)&hp1);
    lo = make_uint2(*(uint32_t*)&lp0, *(uint32_t*)&lp1);
}

// ===========================================================================
// Mask dtype sniffer
// ===========================================================================
__global__ void detect_mask_kernel(const unsigned int* __restrict__ m)
{
    if (threadIdx.x == 0 && blockIdx.x == 0) {
        int all01 = 1, allf = 1;
        for (int i = 0; i < 1024; i++) {
            unsigned int w = m[i];
            if (w > 1u) all01 = 0;
            if (w != 0u && w != 0x3F800000u) allf = 0;
        }
        g_mask_kind = all01 ? 1 : (allf ? 2 : 0);
    }
}

// ===========================================================================
// RoPE cos/sin table build.
// ===========================================================================
__global__ void rope_table_kernel()
{
    int idx = blockIdx.x * blockDim.x + threadIdx.x;   // 65536
    int l = idx >> 5, j = idx & 31;
    float inv = exp2f(-0.41524101186092f * (float)j);
    float freq = (float)l * inv;
    g_rope[l][j] = make_float2(cosf(freq), sinf(freq));
}

// ===========================================================================
// V pre-split: (b,l,h,d) fp32 -> g_vh/g_vl[z][d][k] bf16 (transposed)
// ===========================================================================
__global__ void vsplit_kernel(const float* __restrict__ gv)
{
    __shared__ float t[64][65];
    const int z = blockIdx.y;
    const int b = z >> 4, h = z & 15;
    const int k0 = blockIdx.x * 64;
    for (int i = threadIdx.x; i < 64 * 64; i += 256) {
        int kk = i >> 6, d = i & 63;
        t[kk][d] = gv[(((size_t)(b * L_ + k0 + kk)) * H_ + h) * DK_ + d];
    }
    __syncthreads();
    for (int i = threadIdx.x; i < 64 * 64; i += 256) {
        int d = i >> 6, kk = i & 63;
        float v = t[kk][d];
        __nv_bfloat16 hi = __float2bfloat16(v);
        __nv_bfloat16 lo = __float2bfloat16(v - __bfloat162float(hi));
        g_vh[z][d][k0 + kk] = hi;
        g_vl[z][d][k0 + kk] = lo;
    }
}

// ===========================================================================
// HMMA split-bf16 projection GEMM: C = A @ W^T + bias  (unchanged, proven)
// ===========================================================================
#define PADK 40

__global__ __launch_bounds__(256)
void proj_mma(const float* __restrict__ A0, const float* __restrict__ A1,
              const float* __restrict__ A2,
              const float* __restrict__ W0, const float* __restrict__ W1,
              const float* __restrict__ W2,
              float* __restrict__ C0, float* __restrict__ C1, float* __restrict__ C2,
              const float* __restrict__ bi0, const float* __restrict__ bi1,
              const float* __restrict__ bi2)
{
    const int z = blockIdx.z;
    const float* A    = (z == 0) ? A0 : (z == 1) ? A1 : A2;
    const float* W    = (z == 0) ? W0 : (z == 1) ? W1 : W2;
    float* C          = (z == 0) ? C0 : (z == 1) ? C1 : C2;
    const float* bias = (z == 0) ? bi0 : (z == 1) ? bi1 : bi2;

    __shared__ __nv_bfloat16 sAh[128][PADK], sAl[128][PADK];
    __shared__ __nv_bfloat16 sBh[128][PADK], sBl[128][PADK];

    const int tid  = threadIdx.x;
    const int wid  = tid >> 5, lane = tid & 31;
    const int wm   = wid & 1, wn = wid >> 1;          // 2 x 4 warp grid
    const int m0   = blockIdx.y * 128, n0 = blockIdx.x * 128;

    const uint32_t bAh = smem_u32(sAh), bAl = smem_u32(sAl);
    const uint32_t bBh = smem_u32(sBh), bBl = smem_u32(sBl);

    const uint32_t aoff = (uint32_t)((wm * 64 + (lane & 15)) * PADK + ((lane >> 4) << 3)) * 2;
    const uint32_t boff = (uint32_t)((wn * 32 + (lane & 7) + ((lane >> 4) << 3)) * PADK
                                     + (((lane >> 3) & 1) << 3)) * 2;

    const int lrow = tid >> 3;
    const int lk   = (tid & 7) * 4;

    const float* Ag = A + (size_t)m0 * D_;
    const float* Wg = W + (size_t)n0 * D_;

    float acc[4][4][4] = {};

    for (int kc = 0; kc < D_; kc += 32) {
        __syncthreads();
        #pragma unroll
        for (int it = 0; it < 4; it++) {
            int r = it * 32 + lrow;
            uint2 hi, lo;
            split4(*(const float4*)&Ag[(size_t)r * D_ + kc + lk], hi, lo);
            *(uint2*)&sAh[r][lk] = hi;
            *(uint2*)&sAl[r][lk] = lo;
            split4(*(const float4*)&Wg[(size_t)r * D_ + kc + lk], hi, lo);
            *(uint2*)&sBh[r][lk] = hi;
            *(uint2*)&sBl[r][lk] = lo;
        }
        __syncthreads();

        #pragma unroll
        for (int kb = 0; kb < 32; kb += 16) {
            const uint32_t kbo = (uint32_t)kb * 2;
            uint32_t ah[4][4], al[4][4];
            #pragma unroll
            for (int i = 0; i < 4; i++) {
                uint32_t step = (uint32_t)(i * 16 * PADK) * 2;
                ldsm4(ah[i], bAh + aoff + kbo + step);
                ldsm4(al[i], bAl + aoff + kbo + step);
            }
            uint32_t bh[8], bl[8];
            ldsm4(bh,     bBh + boff + kbo);
            ldsm4(bh + 4, bBh + boff + kbo + (uint32_t)(16 * PADK) * 2);
            ldsm4(bl,     bBl + boff + kbo);
            ldsm4(bl + 4, bBl + boff + kbo + (uint32_t)(16 * PADK) * 2);
            #pragma unroll
            for (int i = 0; i < 4; i++)
                #pragma unroll
                for (int j = 0; j < 4; j++) {
                    mma16816(acc[i][j], ah[i], &bh[j * 2]);
                    mma16816(acc[i][j], ah[i], &bl[j * 2]);
                    mma16816(acc[i][j], al[i], &bh[j * 2]);
                }
        }
    }

    const int g = lane >> 2, tig = lane & 3;
    #pragma unroll
    for (int i = 0; i < 4; i++) {
        int row = m0 + wm * 64 + i * 16 + g;
        #pragma unroll
        for (int j = 0; j < 4; j++) {
            int col = n0 + wn * 32 + j * 8 + tig * 2;
            float2 b2 = *(const float2*)&bias[col];
            float2 o0, o1;
            o0.x = acc[i][j][0] + b2.x;  o0.y = acc[i][j][1] + b2.y;
            o1.x = acc[i][j][2] + b2.x;  o1.y = acc[i][j][3] + b2.y;
            *(float2*)&C[(size_t)row * D_ + col]       = o0;
            *(float2*)&C[(size_t)(row + 8) * D_ + col] = o1;
        }
    }
}

// ---------------------------------------------------------------------------
// RoPE apply in-place on q and k (table-driven).
// ---------------------------------------------------------------------------
__global__ void rope_kernel(float* __restrict__ q, float* __restrict__ k)
{
    int idx = blockIdx.x * blockDim.x + threadIdx.x;
    float* x = (idx >> 21) ? k : q;
    idx &= (1 << 21) - 1;
    int j = idx & 31;
    int h = (idx >> 5) & 15;
    int l = (idx >> 9) & 2047;
    int b = idx >> 20;
    size_t base = (((size_t)(b * L_ + l)) * H_ + h) * DK_;
    float2 cs = g_rope[l][j];
    float a  = x[base + j];
    float bb = x[base + j + 32];
    x[base + j]      = a * cs.x - bb * cs.y;
    x[base + j + 32] = bb * cs.x + a * cs.y;
}

// ===========================================================================
// Kernel A: rowsum_mma. Q.K^T/8, mask, +awb, exp -> rowsum atomics ONLY.
// (proven logits geometry, no weights store, no stage)
// ===========================================================================
__global__ __launch_bounds__(256, 3)
void rowsum_mma(const float* __restrict__ gq,
                const float* __restrict__ gk,
                const void* __restrict__ mask,
                const float* __restrict__ awb)
{
    const int z = blockIdx.z;
    const int h = z >> 1, b = z & 1;
    const int zp = b * H_ + h;
    const float* A  = gq + ((size_t)b * L_ * H_ + h) * DK_;
    const float* Bm = gk + ((size_t)b * L_ * H_ + h) * DK_;
    const float* arow = awb + (size_t)h * L_ * L_;
    const size_t mbase = (size_t)b * L_ * L_;

    const int mk = g_mask_kind;
    const unsigned char* m8  = (const unsigned char*)mask;
    const int*           m32 = (const int*)mask;
    const float*         mf  = (const float*)mask;

    __shared__ __nv_bfloat16 sAh[128][PADK], sAl[128][PADK];
    __shared__ __nv_bfloat16 sBh[64][PADK],  sBl[64][PADK];

    const int tid  = threadIdx.x;
    const int wid  = tid >> 5, lane = tid & 31;
    const int wm   = wid & 1, wn = wid >> 1;
    const int m0   = blockIdx.y * 128, n0 = blockIdx.x * 64;

    const uint32_t bAh = smem_u32(sAh), bAl = smem_u32(sAl);
    const uint32_t bBh = smem_u32(sBh), bBl = smem_u32(sBl);

    const uint32_t aoff = (uint32_t)((wm * 64 + (lane & 15)) * PADK + ((lane >> 4) << 3)) * 2;
    const uint32_t boff = (uint32_t)((wn * 16 + (lane & 7) + ((lane >> 4) << 3)) * PADK
                                     + (((lane >> 3) & 1) << 3)) * 2;

    const int lrow = tid >> 3;
    const int lk   = (tid & 7) * 4;

    float acc[4][2][4] = {};

    for (int kc = 0; kc < DK_; kc += 32) {
        __syncthreads();
        #pragma unroll
        for (int it = 0; it < 4; it++) {
            int r = it * 32 + lrow;
            uint2 hi, lo;
            split4(*(const float4*)&A[(size_t)(m0 + r) * D_ + kc + lk], hi, lo);
            *(uint2*)&sAh[r][lk] = hi;
            *(uint2*)&sAl[r][lk] = lo;
        }
        #pragma unroll
        for (int it = 0; it < 2; it++) {
            int r = it * 32 + lrow;
            uint2 hi, lo;
            split4(*(const float4*)&Bm[(size_t)(n0 + r) * D_ + kc + lk], hi, lo);
            *(uint2*)&sBh[r][lk] = hi;
            *(uint2*)&sBl[r][lk] = lo;
        }
        __syncthreads();

        #pragma unroll
        for (int kb = 0; kb < 32; kb += 16) {
            const uint32_t kbo = (uint32_t)kb * 2;
            uint32_t ah[4][4], al[4][4];
            #pragma unroll
            for (int i = 0; i < 4; i++) {
                uint32_t step = (uint32_t)(i * 16 * PADK) * 2;
                ldsm4(ah[i], bAh + aoff + kbo + step);
                ldsm4(al[i], bAl + aoff + kbo + step);
            }
            uint32_t bh[4], bl[4];
            ldsm4(bh, bBh + boff + kbo);
            ldsm4(bl, bBl + boff + kbo);
            #pragma unroll
            for (int i = 0; i < 4; i++)
                #pragma unroll
                for (int j = 0; j < 2; j++) {
                    mma16816(acc[i][j], ah[i], &bh[j * 2]);
                    mma16816(acc[i][j], ah[i], &bl[j * 2]);
                    mma16816(acc[i][j], al[i], &bh[j * 2]);
                }
        }
    }

    // Epilogue: exp + rowsum only.
    const int g = lane >> 2, tig = lane & 3;
    #pragma unroll
    for (int i = 0; i < 4; i++) {
        float s0 = 0.0f, s1 = 0.0f;
        int row = m0 + wm * 64 + i * 16 + g;
        #pragma unroll
        for (int j = 0; j < 2; j++) {
            int col = n0 + wn * 16 + j * 8 + tig * 2;
            size_t o0 = (size_t)row * L_ + col;
            size_t o1 = (size_t)(row + 8) * L_ + col;
            float2 a0 = *(const float2*)&arow[o0];
            float2 a1 = *(const float2*)&arow[o1];
            float v00 = acc[i][j][0] * 0.125f, v01 = acc[i][j][1] * 0.125f;
            float v10 = acc[i][j][2] * 0.125f, v11 = acc[i][j][3] * 0.125f;
            bool k00, k01, k10, k11;
            if (mk == 1) {
                int2 q0 = *(const int2*)&m32[mbase + o0];
                int2 q1 = *(const int2*)&m32[mbase + o1];
                k00 = q0.x != 0; k01 = q0.y != 0; k10 = q1.x != 0; k11 = q1.y != 0;
            } else if (mk == 2) {
                float2 q0 = *(const float2*)&mf[mbase + o0];
                float2 q1 = *(const float2*)&mf[mbase + o1];
                k00 = q0.x != 0.0f; k01 = q0.y != 0.0f;
                k10 = q1.x != 0.0f; k11 = q1.y != 0.0f;
            } else {
                k00 = m8[mbase + o0] != 0;     k01 = m8[mbase + o0 + 1] != 0;
                k10 = m8[mbase + o1] != 0;     k11 = m8[mbase + o1 + 1] != 0;
            }
            v00 = k00 ? v00 : -1e30f;  v01 = k01 ? v01 : -1e30f;
            v10 = k10 ? v10 : -1e30f;  v11 = k11 ? v11 : -1e30f;
            s0 += __expf(fminf(v00 + a0.x, 80.0f)) + __expf(fminf(v01 + a0.y, 80.0f));
            s1 += __expf(fminf(v10 + a1.x, 80.0f)) + __expf(fminf(v11 + a1.y, 80.0f));
        }
        s0 += __shfl_xor_sync(0xffffffffu, s0, 1);
        s0 += __shfl_xor_sync(0xffffffffu, s0, 2);
        s1 += __shfl_xor_sync(0xffffffffu, s1, 1);
        s1 += __shfl_xor_sync(0xffffffffu, s1, 2);
        if (tig == 0) {
            atomicAdd(&g_rsum[(size_t)zp * L_ + row], s0);
            atomicAdd(&g_rsum[(size_t)zp * L_ + row + 8], s1);
        }
    }
}

// ===========================================================================
// Kernel B: fused_wv. Per (ksplit, 64-row block, z): Q resident; for each of
// 8 column tiles: recompute logits, exp, x(1/rowsum), write final weights,
// split normalized tile -> attn MMA with pre-split V; attn accumulated in
// regs across tiles, flushed once via red.v2.
// Rows padded to 72 bf16 (144B stride, ldmatrix conflict-free).
// ===========================================================================
#define PADK2 72

__global__ __launch_bounds__(256, 2)
void fused_wv(const float* __restrict__ gq,
              const float* __restrict__ gk,
              const void* __restrict__ mask,
              const float* __restrict__ awb,
              float* __restrict__ Wt,
              float* __restrict__ gattn)
{
    const int z = blockIdx.z;
    const int h = z >> 1, b = z & 1;
    const int zp = b * H_ + h;
    const int m0 = blockIdx.y * 64;
    const int kcol0 = blockIdx.x * KCH2;

    const float* Q  = gq + ((size_t)b * L_ * H_ + h) * DK_;
    const float* K  = gk + ((size_t)b * L_ * H_ + h) * DK_;
    const float* arow = awb + (size_t)h * L_ * L_;
    float* C  = Wt + (size_t)zp * L_ * L_;
    float* AT = gattn + (size_t)b * L_ * D_ + h * DK_;
    const size_t mbase = (size_t)b * L_ * L_;

    const int mk = g_mask_kind;
    const unsigned char* m8  = (const unsigned char*)mask;
    const int*           m32 = (const int*)mask;
    const float*         mf  = (const float*)mask;

    __shared__ __nv_bfloat16 sQh[64][PADK2], sQl[64][PADK2];
    __shared__ __nv_bfloat16 sKh[64][PADK2], sKl[64][PADK2];
    __shared__ __nv_bfloat16 sVh[64][PADK2], sVl[64][PADK2];
    __shared__ __nv_bfloat16 sWh[64][PADK2], sWl[64][PADK2];
    __shared__ float sC[64][68];
    __shared__ float inv_s[64];

    const int tid  = threadIdx.x;
    const int wid  = tid >> 5, lane = tid & 31;
    const int wm2  = wid & 1, wn2 = wid >> 1;    // 2 x 4 warps: 32 rows x 16 cols

    const uint32_t bQh = smem_u32(sQh), bQl = smem_u32(sQl);
    const uint32_t bKh = smem_u32(sKh), bKl = smem_u32(sKl);
    const uint32_t bVh = smem_u32(sVh), bVl = smem_u32(sVl);
    const uint32_t bWh = smem_u32(sWh), bWl = smem_u32(sWl);

    const uint32_t aoff = (uint32_t)((wm2 * 32 + (lane & 15)) * PADK2 + ((lane >> 4) << 3)) * 2;
    const uint32_t boff = (uint32_t)((wn2 * 16 + (lane & 7) + ((lane >> 4) << 3)) * PADK2
                                     + (((lane >> 3) & 1) << 3)) * 2;

    const int lrow = tid >> 2;           // 0..63
    const int lk   = (tid & 3) * 4;      // 0..12, x4 iters covers 64

    // Load Q tile (64 rows x 64 k), split into resident smem; load inv rowsums.
    #pragma unroll
    for (int it = 0; it < 4; it++) {
        uint2 hi, lo;
        split4(*(const float4*)&Q[(size_t)(m0 + lrow) * D_ + lk + it * 16], hi, lo);
        *(uint2*)&sQh[lrow][lk + it * 16] = hi;
        *(uint2*)&sQl[lrow][lk + it * 16] = lo;
    }
    if (tid < 64) inv_s[tid] = 1.0f / g_rsum[(size_t)zp * L_ + m0 + tid];
    __syncthreads();

    float acc_a[2][2][4] = {};
    const int g = lane >> 2, tig = lane & 3;
    const int srow = tid >> 4, scol = (tid & 15) * 4;

    for (int ct = 0; ct < KCH2 / 64; ct++) {
        const int n0t = kcol0 + ct * 64;

        // Load K tile (64 key-rows x 64 k)
        #pragma unroll
        for (int it = 0; it < 4; it++) {
            uint2 hi, lo;
            split4(*(const float4*)&K[(size_t)(n0t + lrow) * D_ + lk + it * 16], hi, lo);
            *(uint2*)&sKh[lrow][lk + it * 16] = hi;
            *(uint2*)&sKl[lrow][lk + it * 16] = lo;
        }
        __syncthreads();

        // Logits MMA: 64x64 tile, K dim 64 in 4 kb of 16.
        float acc_l[2][2][4] = {};
        #pragma unroll
        for (int kb = 0; kb < 64; kb += 16) {
            const uint32_t kbo = (uint32_t)kb * 2;
            uint32_t ah[2][4], al[2][4];
            #pragma unroll
            for (int i = 0; i < 2; i++) {
                uint32_t step = (uint32_t)(i * 16 * PADK2) * 2;
                ldsm4(ah[i], bQh + aoff + kbo + step);
                ldsm4(al[i], bQl + aoff + kbo + step);
            }
            uint32_t bh[4], bl[4];
            ldsm4(bh, bKh + boff + kbo);
            ldsm4(bl, bKl + boff + kbo);
            #pragma unroll
            for (int i = 0; i < 2; i++)
                #pragma unroll
                for (int j = 0; j < 2; j++) {
                    mma16816(acc_l[i][j], ah[i], &bh[j * 2]);
                    mma16816(acc_l[i][j], ah[i], &bl[j * 2]);
                    mma16816(acc_l[i][j], al[i], &bh[j * 2]);
                }
        }

        // Stage raw logits
        #pragma unroll
        for (int i = 0; i < 2; i++) {
            int row = wm2 * 32 + i * 16 + g;
            #pragma unroll
            for (int j = 0; j < 2; j++) {
                int col = wn2 * 16 + j * 8 + tig * 2;
                *(float2*)&sC[row][col]     = make_float2(acc_l[i][j][0], acc_l[i][j][1]);
                *(float2*)&sC[row + 8][col] = make_float2(acc_l[i][j][2], acc_l[i][j][3]);
            }
        }
        __syncthreads();

        // Stream: 4 passes of 16 rows; write final weights + build W planes.
        #pragma unroll
        for (int p = 0; p < 4; p++) {
            int row = p * 16 + srow;
            int grow = m0 + row;
            size_t o = (size_t)grow * L_ + n0t + scol;
            float4 v = *(const float4*)&sC[row][scol];
            v.x *= 0.125f; v.y *= 0.125f; v.z *= 0.125f; v.w *= 0.125f;
            bool k0, k1, k2, k3;
            if (mk == 1) {
                int4 mm = *(const int4*)&m32[mbase + o];
                k0 = mm.x != 0; k1 = mm.y != 0; k2 = mm.z != 0; k3 = mm.w != 0;
            } else if (mk == 2) {
                float4 mm = *(const float4*)&mf[mbase + o];
                k0 = mm.x != 0.0f; k1 = mm.y != 0.0f; k2 = mm.z != 0.0f; k3 = mm.w != 0.0f;
            } else {
                uchar4 mm = *(const uchar4*)&m8[mbase + o];
                k0 = mm.x != 0; k1 = mm.y != 0; k2 = mm.z != 0; k3 = mm.w != 0;
            }
            float4 a = *(const float4*)&arow[o];
            float iv = inv_s[row];
            float4 e;
            e.x = __expf(fminf((k0 ? v.x : -1e30f) + a.x, 80.0f)) * iv;
            e.y = __expf(fminf((k1 ? v.y : -1e30f) + a.y, 80.0f)) * iv;
            e.z = __expf(fminf((k2 ? v.z : -1e30f) + a.z, 80.0f)) * iv;
            e.w = __expf(fminf((k3 ? v.w : -1e30f) + a.w, 80.0f)) * iv;
            *(float4*)&C[o] = e;
            uint2 hi, lo;
            split4(e, hi, lo);
            *(uint2*)&sWh[row][scol] = hi;
            *(uint2*)&sWl[row][scol] = lo;
        }

        // Load V tile: 64 d-rows x 64 k bf16 (pre-split planes), uint4 copies.
        for (int i2 = tid; i2 < 64 * 8; i2 += 256) {
            int vr = i2 >> 3, vq = (i2 & 7) * 8;
            *(uint4*)&sVh[vr][vq] = *(const uint4*)&g_vh[zp][vr][n0t + vq];
            *(uint4*)&sVl[vr][vq] = *(const uint4*)&g_vl[zp][vr][n0t + vq];
        }
        __syncthreads();

        // Attn MMA: acc_a += W(64x64) @ V^T(64d x 64k)
        #pragma unroll
        for (int kb = 0; kb < 64; kb += 16) {
            const uint32_t kbo = (uint32_t)kb * 2;
            uint32_t ah[2][4], al[2][4];
            #pragma unroll
            for (int i = 0; i < 2; i++) {
                uint32_t step = (uint32_t)(i * 16 * PADK2) * 2;
                ldsm4(ah[i], bWh + aoff + kbo + step);
                ldsm4(al[i], bWl + aoff + kbo + step);
            }
            uint32_t bh[4], bl[4];
            ldsm4(bh, bVh + boff + kbo);
            ldsm4(bl, bVl + boff + kbo);
            #pragma unroll
            for (int i = 0; i < 2; i++)
                #pragma unroll
                for (int j = 0; j < 2; j++) {
                    mma16816(acc_a[i][j], ah[i], &bh[j * 2]);
                    mma16816(acc_a[i][j], ah[i], &bl[j * 2]);
                    mma16816(acc_a[i][j], al[i], &bh[j * 2]);
                }
        }
        __syncthreads();
    }

    // Flush attn partials (one RED pass per block)
    #pragma unroll
    for (int i = 0; i < 2; i++) {
        int row = m0 + wm2 * 32 + i * 16 + g;
        #pragma unroll
        for (int j = 0; j < 2; j++) {
            int col = wn2 * 16 + j * 8 + tig * 2;
            red_add_v2(&AT[(size_t)row * D_ + col],       acc_a[i][j][0], acc_a[i][j][1]);
            red_add_v2(&AT[(size_t)(row + 8) * D_ + col], acc_a[i][j][2], acc_a[i][j][3]);
        }
    }
}

// ---------------------------------------------------------------------------
extern "C" void kernel_launch(void* const* d_in, const int* in_sizes, int n_in,
                              void* d_out, int out_size)
{
    const float* query = (const float*)d_in[0];
    const float* key   = (const float*)d_in[1];
    const float* value = (const float*)d_in[2];
    const void*  mask  = d_in[3];
    const float* awb = (const float*)d_in[4];
    const float* Wq = (const float*)d_in[5];
    const float* bq = (const float*)d_in[6];
    const float* Wk = (const float*)d_in[7];
    const float* bk = (const float*)d_in[8];
    const float* Wv = (const float*)d_in[9];
    const float* bv = (const float*)d_in[10];
    const float* Wo = (const float*)d_in[11];
    const float* bo = (const float*)d_in[12];

    float* out = (float*)d_out;                              // (B, L, D)
    float* weights = out + (size_t)B_ * L_ * D_;             // (B, H, L, L)

    float *gq, *gk, *gv, *gattn, *grsum;
    cudaGetSymbolAddress((void**)&gq, g_q);
    cudaGetSymbolAddress((void**)&gk, g_k);
    cudaGetSymbolAddress((void**)&gv, g_v);
    cudaGetSymbolAddress((void**)&gattn, g_attn);
    cudaGetSymbolAddress((void**)&grsum, g_rsum);

    dim3 blk(256);

    // 0) mask dtype sniff + rope table + zero accumulators
    detect_mask_kernel<<<1, 32>>>((const unsigned int*)mask);
    rope_table_kernel<<<(L_ * 32) / 256, 256>>>();
    cudaMemsetAsync(grsum, 0, (size_t)B_ * H_ * L_ * sizeof(float));
    cudaMemsetAsync(gattn, 0, (size_t)ML_ * D_ * sizeof(float));

    // 1) QKV projections via HMMA split-bf16
    dim3 gproj(D_ / 128, ML_ / 128, 3);
    proj_mma<<<gproj, blk>>>(query, key, value, Wq, Wk, Wv,
                             gq, gk, gv, bq, bk, bv);

    // 2) RoPE on q and k (table-driven); V pre-split/transpose
    rope_kernel<<<2 * (B_ * L_ * H_ * 32) / 256, 256>>>(gq, gk);
    dim3 gvs(L_ / 64, B_ * H_);
    vsplit_kernel<<<gvs, blk>>>(gv);

    // 3) Kernel A: rowsums only
    dim3 grs(L_ / 64, L_ / 128, B_ * H_);                    // 32 x 16 x 32
    rowsum_mma<<<grs, blk>>>(gq, gk, mask, awb);

    // 4) Kernel B: recompute + normalize + write weights + attn
    dim3 gfw(KSPLIT2, L_ / 64, B_ * H_);                     // 4 x 32 x 32
    fused_wv<<<gfw, blk>>>(gq, gk, mask, awb, weights, gattn);

    // 5) Output projection via HMMA
    dim3 gout(D_ / 128, ML_ / 128, 1);
    proj_mma<<<gout, blk>>>(gattn, gattn, gattn, Wo, Wo, Wo,
                            out, out, out, bo, bo, bo);
}

// round 17
// speedup vs baseline: 1.5903x; 1.5903x over previous
#include <cuda_runtime.h>
#include <cuda_bf16.h>
#include <math.h>
#include <stdint.h>

// Problem constants
#define B_  2
#define L_  2048
#define H_  16
#define DK_ 64
#define D_  (H_ * DK_)        // 1024
#define ML_ (B_ * L_)         // 4096
#define KSPLIT 8
#define KCH (L_ / KSPLIT)     // 256

// Scratch (device globals: no allocation allowed)
__device__ float g_q[(size_t)ML_ * D_];
__device__ float g_k[(size_t)ML_ * D_];
__device__ float g_v[(size_t)ML_ * D_];
__device__ float g_attn[(size_t)ML_ * D_];
__device__ float g_rsum[(size_t)B_ * H_ * L_];
__device__ float2 g_rope[L_][32];
__device__ __nv_bfloat16 g_qh[(size_t)ML_ * D_];   // Q rope'd, split hi
__device__ __nv_bfloat16 g_ql[(size_t)ML_ * D_];   // Q rope'd, split lo
__device__ __nv_bfloat16 g_kh[(size_t)ML_ * D_];   // K rope'd, split hi
__device__ __nv_bfloat16 g_kl[(size_t)ML_ * D_];   // K rope'd, split lo
__device__ __nv_bfloat16 g_vh[B_ * H_][DK_][L_];   // V split hi, n-major
__device__ __nv_bfloat16 g_vl[B_ * H_][DK_][L_];   // V split lo, n-major
__device__ int   g_mask_kind;   // 0 = uint8, 1 = int32, 2 = float32

// ===========================================================================
// Helpers
// ===========================================================================
__device__ __forceinline__ uint32_t smem_u32(const void* p) {
    uint32_t a;
    asm("{ .reg .u64 t; cvta.to.shared.u64 t, %1; cvt.u32.u64 %0, t; }"
        : "=r"(a) : "l"(p));
    return a;
}

__device__ __forceinline__ void ldsm4(uint32_t* r, uint32_t addr) {
    asm volatile("ldmatrix.sync.aligned.m8n8.x4.shared.b16 {%0,%1,%2,%3}, [%4];"
                 : "=r"(r[0]), "=r"(r[1]), "=r"(r[2]), "=r"(r[3]) : "r"(addr));
}

__device__ __forceinline__ void mma16816(float* c, const uint32_t* a, const uint32_t* b) {
    asm volatile(
        "mma.sync.aligned.m16n8k16.row.col.f32.bf16.bf16.f32 "
        "{%0,%1,%2,%3}, {%4,%5,%6,%7}, {%8,%9}, {%0,%1,%2,%3};"
        : "+f"(c[0]), "+f"(c[1]), "+f"(c[2]), "+f"(c[3])
        : "r"(a[0]), "r"(a[1]), "r"(a[2]), "r"(a[3]), "r"(b[0]), "r"(b[1]));
}

__device__ __forceinline__ void red_add_v2(float* p, float a, float b) {
    asm volatile("red.global.add.v2.f32 [%0], {%1, %2};"
                 :: "l"(p), "f"(a), "f"(b) : "memory");
}

// Split fp32 float4 -> packed hi / lo bf16x2 pairs (uint2 each)
__device__ __forceinline__ void split4(float4 v, uint2& hi, uint2& lo) {
    __nv_bfloat16 h0 = __float2bfloat16(v.x), h1 = __float2bfloat16(v.y),
                  h2 = __float2bfloat16(v.z), h3 = __float2bfloat16(v.w);
    __nv_bfloat16 l0 = __float2bfloat16(v.x - __bfloat162float(h0)),
                  l1 = __float2bfloat16(v.y - __bfloat162float(h1)),
                  l2 = __float2bfloat16(v.z - __bfloat162float(h2)),
                  l3 = __float2bfloat16(v.w - __bfloat162float(h3));
    __nv_bfloat162 hp0 = __halves2bfloat162(h0, h1);
    __nv_bfloat162 hp1 = __halves2bfloat162(h2, h3);
    __nv_bfloat162 lp0 = __halves2bfloat162(l0, l1);
    __nv_bfloat162 lp1 = __halves2bfloat162(l2, l3);
    hi = make_uint2(*(uint32_t*)&hp0, *(uint32_t*)&hp1);
    lo = make_uint2(*(uint32_t*)&lp0, *(uint32_t*)&lp1);
}

// ===========================================================================
// Mask dtype sniffer
// ===========================================================================
__global__ void detect_mask_kernel(const unsigned int* __restrict__ m)
{
    if (threadIdx.x == 0 && blockIdx.x == 0) {
        int all01 = 1, allf = 1;
        for (int i = 0; i < 1024; i++) {
            unsigned int w = m[i];
            if (w > 1u) all01 = 0;
            if (w != 0u && w != 0x3F800000u) allf = 0;
        }
        g_mask_kind = all01 ? 1 : (allf ? 2 : 0);
    }
}

// ===========================================================================
// RoPE cos/sin table build.
// ===========================================================================
__global__ void rope_table_kernel()
{
    int idx = blockIdx.x * blockDim.x + threadIdx.x;   // 65536
    int l = idx >> 5, j = idx & 31;
    float inv = exp2f(-0.41524101186092f * (float)j);
    float freq = (float)l * inv;
    g_rope[l][j] = make_float2(cosf(freq), sinf(freq));
}

// ===========================================================================
// V pre-split: (b,l,h,d) fp32 -> g_vh/g_vl[z][d][k] bf16 (transposed)
// ===========================================================================
__global__ void vsplit_kernel(const float* __restrict__ gv)
{
    __shared__ float t[64][65];
    const int z = blockIdx.y;
    const int b = z >> 4, h = z & 15;
    const int k0 = blockIdx.x * 64;
    for (int i = threadIdx.x; i < 64 * 64; i += 256) {
        int kk = i >> 6, d = i & 63;
        t[kk][d] = gv[(((size_t)(b * L_ + k0 + kk)) * H_ + h) * DK_ + d];
    }
    __syncthreads();
    for (int i = threadIdx.x; i < 64 * 64; i += 256) {
        int d = i >> 6, kk = i & 63;
        float v = t[kk][d];
        __nv_bfloat16 hi = __float2bfloat16(v);
        __nv_bfloat16 lo = __float2bfloat16(v - __bfloat162float(hi));
        g_vh[z][d][k0 + kk] = hi;
        g_vl[z][d][k0 + kk] = lo;
    }
}

// ===========================================================================
// HMMA split-bf16 projection GEMM: C = A @ W^T + bias  (unchanged, proven)
// ===========================================================================
#define PADK 40

__global__ __launch_bounds__(256)
void proj_mma(const float* __restrict__ A0, const float* __restrict__ A1,
              const float* __restrict__ A2,
              const float* __restrict__ W0, const float* __restrict__ W1,
              const float* __restrict__ W2,
              float* __restrict__ C0, float* __restrict__ C1, float* __restrict__ C2,
              const float* __restrict__ bi0, const float* __restrict__ bi1,
              const float* __restrict__ bi2)
{
    const int z = blockIdx.z;
    const float* A    = (z == 0) ? A0 : (z == 1) ? A1 : A2;
    const float* W    = (z == 0) ? W0 : (z == 1) ? W1 : W2;
    float* C          = (z == 0) ? C0 : (z == 1) ? C1 : C2;
    const float* bias = (z == 0) ? bi0 : (z == 1) ? bi1 : bi2;

    __shared__ __nv_bfloat16 sAh[128][PADK], sAl[128][PADK];
    __shared__ __nv_bfloat16 sBh[128][PADK], sBl[128][PADK];

    const int tid  = threadIdx.x;
    const int wid  = tid >> 5, lane = tid & 31;
    const int wm   = wid & 1, wn = wid >> 1;          // 2 x 4 warp grid
    const int m0   = blockIdx.y * 128, n0 = blockIdx.x * 128;

    const uint32_t bAh = smem_u32(sAh), bAl = smem_u32(sAl);
    const uint32_t bBh = smem_u32(sBh), bBl = smem_u32(sBl);

    const uint32_t aoff = (uint32_t)((wm * 64 + (lane & 15)) * PADK + ((lane >> 4) << 3)) * 2;
    const uint32_t boff = (uint32_t)((wn * 32 + (lane & 7) + ((lane >> 4) << 3)) * PADK
                                     + (((lane >> 3) & 1) << 3)) * 2;

    const int lrow = tid >> 3;
    const int lk   = (tid & 7) * 4;

    const float* Ag = A + (size_t)m0 * D_;
    const float* Wg = W + (size_t)n0 * D_;

    float acc[4][4][4] = {};

    for (int kc = 0; kc < D_; kc += 32) {
        __syncthreads();
        #pragma unroll
        for (int it = 0; it < 4; it++) {
            int r = it * 32 + lrow;
            uint2 hi, lo;
            split4(*(const float4*)&Ag[(size_t)r * D_ + kc + lk], hi, lo);
            *(uint2*)&sAh[r][lk] = hi;
            *(uint2*)&sAl[r][lk] = lo;
            split4(*(const float4*)&Wg[(size_t)r * D_ + kc + lk], hi, lo);
            *(uint2*)&sBh[r][lk] = hi;
            *(uint2*)&sBl[r][lk] = lo;
        }
        __syncthreads();

        #pragma unroll
        for (int kb = 0; kb < 32; kb += 16) {
            const uint32_t kbo = (uint32_t)kb * 2;
            uint32_t ah[4][4], al[4][4];
            #pragma unroll
            for (int i = 0; i < 4; i++) {
                uint32_t step = (uint32_t)(i * 16 * PADK) * 2;
                ldsm4(ah[i], bAh + aoff + kbo + step);
                ldsm4(al[i], bAl + aoff + kbo + step);
            }
            uint32_t bh[8], bl[8];
            ldsm4(bh,     bBh + boff + kbo);
            ldsm4(bh + 4, bBh + boff + kbo + (uint32_t)(16 * PADK) * 2);
            ldsm4(bl,     bBl + boff + kbo);
            ldsm4(bl + 4, bBl + boff + kbo + (uint32_t)(16 * PADK) * 2);
            #pragma unroll
            for (int i = 0; i < 4; i++)
                #pragma unroll
                for (int j = 0; j < 4; j++) {
                    mma16816(acc[i][j], ah[i], &bh[j * 2]);
                    mma16816(acc[i][j], ah[i], &bl[j * 2]);
                    mma16816(acc[i][j], al[i], &bh[j * 2]);
                }
        }
    }

    const int g = lane >> 2, tig = lane & 3;
    #pragma unroll
    for (int i = 0; i < 4; i++) {
        int row = m0 + wm * 64 + i * 16 + g;
        #pragma unroll
        for (int j = 0; j < 4; j++) {
            int col = n0 + wn * 32 + j * 8 + tig * 2;
            float2 b2 = *(const float2*)&bias[col];
            float2 o0, o1;
            o0.x = acc[i][j][0] + b2.x;  o0.y = acc[i][j][1] + b2.y;
            o1.x = acc[i][j][2] + b2.x;  o1.y = acc[i][j][3] + b2.y;
            *(float2*)&C[(size_t)row * D_ + col]       = o0;
            *(float2*)&C[(size_t)(row + 8) * D_ + col] = o1;
        }
    }
}

// ---------------------------------------------------------------------------
// RoPE apply + split: read fp32 q/k, rotate, write bf16 hi/lo planes.
// (fp32 q/k buffers are not written back; only logits consumed them.)
// ---------------------------------------------------------------------------
__global__ void rope_split_kernel(const float* __restrict__ q,
                                  const float* __restrict__ k)
{
    int idx = blockIdx.x * blockDim.x + threadIdx.x;
    const int which = idx >> 21;
    const float* x = which ? k : q;
    __nv_bfloat16* xh = which ? g_kh : g_qh;
    __nv_bfloat16* xl = which ? g_kl : g_ql;
    idx &= (1 << 21) - 1;
    int j = idx & 31;
    int h = (idx >> 5) & 15;
    int l = (idx >> 9) & 2047;
    int b = idx >> 20;
    size_t base = (((size_t)(b * L_ + l)) * H_ + h) * DK_;
    float2 cs = g_rope[l][j];
    float a  = x[base + j];
    float bb = x[base + j + 32];
    float r0 = a * cs.x - bb * cs.y;
    float r1 = bb * cs.x + a * cs.y;
    __nv_bfloat16 h0 = __float2bfloat16(r0);
    __nv_bfloat16 h1 = __float2bfloat16(r1);
    xh[base + j]      = h0;
    xh[base + j + 32] = h1;
    xl[base + j]      = __float2bfloat16(r0 - __bfloat162float(h0));
    xl[base + j + 32] = __float2bfloat16(r1 - __bfloat162float(h1));
}

// ===========================================================================
// HMMA logits, 128x64 tile, smem-staged epilogue (all gmem I/O 16B).
// Q/K come pre-split (uint2 plane copies -> smem).
// ===========================================================================
#define STAGE_BYTES (128 * 68 * 4)   // 34816

__global__ __launch_bounds__(256, 3)
void logits_mma(const void* __restrict__ mask,
                const float* __restrict__ awb,
                float* __restrict__ Wt)
{
    const int z = blockIdx.z;
    const int h = z >> 1, b = z & 1;
    const int zp = b * H_ + h;
    const size_t qkoff = ((size_t)b * L_ * H_ + h) * DK_;     // lda = D_
    const __nv_bfloat16* Ah = g_qh + qkoff;
    const __nv_bfloat16* Al = g_ql + qkoff;
    const __nv_bfloat16* Bh = g_kh + qkoff;
    const __nv_bfloat16* Bl = g_kl + qkoff;
    const float* arow = awb + (size_t)h * L_ * L_;
    float* C = Wt + (size_t)zp * L_ * L_;
    const size_t mbase = (size_t)b * L_ * L_;

    const int mk = g_mask_kind;
    const unsigned char* m8  = (const unsigned char*)mask;
    const int*           m32 = (const int*)mask;
    const float*         mf  = (const float*)mask;

    __shared__ __align__(16) char smem_raw[STAGE_BYTES];
    __nv_bfloat16 (*sAh)[PADK] = (__nv_bfloat16(*)[PADK])(smem_raw);
    __nv_bfloat16 (*sAl)[PADK] = (__nv_bfloat16(*)[PADK])(smem_raw + 10240);
    __nv_bfloat16 (*sBh)[PADK] = (__nv_bfloat16(*)[PADK])(smem_raw + 20480);
    __nv_bfloat16 (*sBl)[PADK] = (__nv_bfloat16(*)[PADK])(smem_raw + 25600);
    float (*sC)[68] = (float(*)[68])smem_raw;

    const int tid  = threadIdx.x;
    const int wid  = tid >> 5, lane = tid & 31;
    const int wm   = wid & 1, wn = wid >> 1;           // 2 x 4; 64 rows x 16 cols
    const int m0   = blockIdx.y * 128, n0 = blockIdx.x * 64;

    const uint32_t bAh = smem_u32(sAh), bAl = smem_u32(sAl);
    const uint32_t bBh = smem_u32(sBh), bBl = smem_u32(sBl);

    const uint32_t aoff = (uint32_t)((wm * 64 + (lane & 15)) * PADK + ((lane >> 4) << 3)) * 2;
    const uint32_t boff = (uint32_t)((wn * 16 + (lane & 7) + ((lane >> 4) << 3)) * PADK
                                     + (((lane >> 3) & 1) << 3)) * 2;

    const int lrow = tid >> 3;
    const int lk   = (tid & 7) * 4;

    float acc[4][2][4] = {};

    for (int kc = 0; kc < DK_; kc += 32) {
        __syncthreads();
        #pragma unroll
        for (int it = 0; it < 4; it++) {
            int r = it * 32 + lrow;
            size_t o = (size_t)(m0 + r) * D_ + kc + lk;
            *(uint2*)&sAh[r][lk] = *(const uint2*)&Ah[o];
            *(uint2*)&sAl[r][lk] = *(const uint2*)&Al[o];
        }
        #pragma unroll
        for (int it = 0; it < 2; it++) {
            int r = it * 32 + lrow;
            size_t o = (size_t)(n0 + r) * D_ + kc + lk;
            *(uint2*)&sBh[r][lk] = *(const uint2*)&Bh[o];
            *(uint2*)&sBl[r][lk] = *(const uint2*)&Bl[o];
        }
        __syncthreads();

        #pragma unroll
        for (int kb = 0; kb < 32; kb += 16) {
            const uint32_t kbo = (uint32_t)kb * 2;
            uint32_t ah[4][4], al[4][4];
            #pragma unroll
            for (int i = 0; i < 4; i++) {
                uint32_t step = (uint32_t)(i * 16 * PADK) * 2;
                ldsm4(ah[i], bAh + aoff + kbo + step);
                ldsm4(al[i], bAl + aoff + kbo + step);
            }
            uint32_t bh[4], bl[4];
            ldsm4(bh, bBh + boff + kbo);
            ldsm4(bl, bBl + boff + kbo);
            #pragma unroll
            for (int i = 0; i < 4; i++)
                #pragma unroll
                for (int j = 0; j < 2; j++) {
                    mma16816(acc[i][j], ah[i], &bh[j * 2]);
                    mma16816(acc[i][j], ah[i], &bl[j * 2]);
                    mma16816(acc[i][j], al[i], &bh[j * 2]);
                }
        }
    }

    // Stage raw logits tile into smem (overlaying dead MMA buffers).
    __syncthreads();
    const int g = lane >> 2, tig = lane & 3;
    #pragma unroll
    for (int i = 0; i < 4; i++) {
        int row = wm * 64 + i * 16 + g;
        #pragma unroll
        for (int j = 0; j < 2; j++) {
            int col = wn * 16 + j * 8 + tig * 2;
            *(float2*)&sC[row][col]     = make_float2(acc[i][j][0], acc[i][j][1]);
            *(float2*)&sC[row + 8][col] = make_float2(acc[i][j][2], acc[i][j][3]);
        }
    }
    __syncthreads();

    // Stream out: 16 rows per pass, 8 passes; all gmem ops are 16B.
    const int srow = tid >> 4, scol = (tid & 15) * 4;
    #pragma unroll
    for (int p = 0; p < 8; p++) {
        int row = p * 16 + srow;
        int grow = m0 + row;
        size_t o = (size_t)grow * L_ + n0 + scol;
        float4 v = *(const float4*)&sC[row][scol];
        v.x *= 0.125f; v.y *= 0.125f; v.z *= 0.125f; v.w *= 0.125f;
        bool k0, k1, k2, k3;
        if (mk == 1) {
            int4 mm = *(const int4*)&m32[mbase + o];
            k0 = mm.x != 0; k1 = mm.y != 0; k2 = mm.z != 0; k3 = mm.w != 0;
        } else if (mk == 2) {
            float4 mm = *(const float4*)&mf[mbase + o];
            k0 = mm.x != 0.0f; k1 = mm.y != 0.0f; k2 = mm.z != 0.0f; k3 = mm.w != 0.0f;
        } else {
            uchar4 mm = *(const uchar4*)&m8[mbase + o];
            k0 = mm.x != 0; k1 = mm.y != 0; k2 = mm.z != 0; k3 = mm.w != 0;
        }
        float4 a = *(const float4*)&arow[o];
        float4 e;
        e.x = __expf(fminf((k0 ? v.x : -1e30f) + a.x, 80.0f));
        e.y = __expf(fminf((k1 ? v.y : -1e30f) + a.y, 80.0f));
        e.z = __expf(fminf((k2 ? v.z : -1e30f) + a.z, 80.0f));
        e.w = __expf(fminf((k3 ? v.w : -1e30f) + a.w, 80.0f));
        *(float4*)&C[o] = e;
        float s = (e.x + e.y) + (e.z + e.w);
        s += __shfl_xor_sync(0xffffffffu, s, 1);
        s += __shfl_xor_sync(0xffffffffu, s, 2);
        s += __shfl_xor_sync(0xffffffffu, s, 4);
        s += __shfl_xor_sync(0xffffffffu, s, 8);
        if ((tid & 15) == 0)
            atomicAdd(&g_rsum[(size_t)zp * L_ + grow], s);
    }
}

// ===========================================================================
// HMMA attnv, split-K x8, register-prefetch double buffered (R15, proven).
// ===========================================================================
__global__ __launch_bounds__(256, 2)
void attnv_mma(float* __restrict__ Wt, float* __restrict__ gattn)
{
    const int z = blockIdx.z;
    const int kch = blockIdx.x;
    const int b = z >> 4, h = z & 15;
    float* A = Wt + (size_t)z * L_ * L_;                        // lda = L_
    float* C = gattn + (size_t)b * L_ * D_ + h * DK_;           // ldc = D_

    __shared__ __nv_bfloat16 sAh[128][PADK], sAl[128][PADK];
    __shared__ __nv_bfloat16 sVh[64][PADK],  sVl[64][PADK];
    __shared__ float inv_s[128];

    const int tid  = threadIdx.x;
    const int wid  = tid >> 5, lane = tid & 31;
    const int wm   = wid & 3, wn = wid >> 2;          // 4 x 2 warp grid
    const int m0   = blockIdx.y * 128;

    const uint32_t bAh = smem_u32(sAh), bAl = smem_u32(sAl);
    const uint32_t bVh = smem_u32(sVh), bVl = smem_u32(sVl);

    const uint32_t aoff = (uint32_t)((wm * 32 + (lane & 15)) * PADK + ((lane >> 4) << 3)) * 2;
    const uint32_t boff = (uint32_t)((wn * 32 + (lane & 7) + ((lane >> 4) << 3)) * PADK
                                     + (((lane >> 3) & 1) << 3)) * 2;

    const int lrow = tid >> 3;           // A: 32 rows per iter
    const int lk   = (tid & 7) * 4;
    const int vn   = tid >> 2;           // V: row 0..63
    const int vkp  = (tid & 3) * 8;      // 8 bf16 per thread

    if (tid < 128) inv_s[tid] = 1.0f / g_rsum[(size_t)z * L_ + m0 + tid];
    __syncthreads();

    const int kc0 = kch * KCH, kcend = kc0 + KCH;

    // Prefetch first chunk
    float4 pa[4];
    uint4 pvh, pvl;
    #pragma unroll
    for (int it = 0; it < 4; it++)
        pa[it] = *(const float4*)&A[(size_t)(m0 + it * 32 + lrow) * L_ + kc0 + lk];
    pvh = *(const uint4*)&g_vh[z][vn][kc0 + vkp];
    pvl = *(const uint4*)&g_vl[z][vn][kc0 + vkp];

    float acc[2][4][4] = {};

    for (int kc = kc0; kc < kcend; kc += 32) {
        // Store phase: normalize + writeback + split A; copy V.
        #pragma unroll
        for (int it = 0; it < 4; it++) {
            int r = it * 32 + lrow;
            float4 v = pa[it];
            float iv = inv_s[r];
            v.x *= iv; v.y *= iv; v.z *= iv; v.w *= iv;
            *(float4*)&A[(size_t)(m0 + r) * L_ + kc + lk] = v;
            uint2 hi, lo;
            split4(v, hi, lo);
            *(uint2*)&sAh[r][lk] = hi;
            *(uint2*)&sAl[r][lk] = lo;
        }
        *(uint4*)&sVh[vn][vkp] = pvh;
        *(uint4*)&sVl[vn][vkp] = pvl;
        __syncthreads();

        // Prefetch next chunk (overlaps the MMA section below)
        int kn = kc + 32;
        if (kn < kcend) {
            #pragma unroll
            for (int it = 0; it < 4; it++)
                pa[it] = *(const float4*)&A[(size_t)(m0 + it * 32 + lrow) * L_ + kn + lk];
            pvh = *(const uint4*)&g_vh[z][vn][kn + vkp];
            pvl = *(const uint4*)&g_vl[z][vn][kn + vkp];
        }

        #pragma unroll
        for (int kb = 0; kb < 32; kb += 16) {
            const uint32_t kbo = (uint32_t)kb * 2;
            uint32_t ah[2][4], al[2][4];
            #pragma unroll
            for (int i = 0; i < 2; i++) {
                uint32_t step = (uint32_t)(i * 16 * PADK) * 2;
                ldsm4(ah[i], bAh + aoff + kbo + step);
                ldsm4(al[i], bAl + aoff + kbo + step);
            }
            uint32_t bh[8], bl[8];
            ldsm4(bh,     bVh + boff + kbo);
            ldsm4(bh + 4, bVh + boff + kbo + (uint32_t)(16 * PADK) * 2);
            ldsm4(bl,     bVl + boff + kbo);
            ldsm4(bl + 4, bVl + boff + kbo + (uint32_t)(16 * PADK) * 2);
            #pragma unroll
            for (int i = 0; i < 2; i++)
                #pragma unroll
                for (int j = 0; j < 4; j++) {
                    mma16816(acc[i][j], ah[i], &bh[j * 2]);
                    mma16816(acc[i][j], ah[i], &bl[j * 2]);
                    mma16816(acc[i][j], al[i], &bh[j * 2]);
                }
        }
        __syncthreads();
    }

    const int g = lane >> 2, tig = lane & 3;
    #pragma unroll
    for (int i = 0; i < 2; i++) {
        int row = m0 + wm * 32 + i * 16 + g;
        #pragma unroll
        for (int j = 0; j < 4; j++) {
            int col = wn * 32 + j * 8 + tig * 2;
            red_add_v2(&C[(size_t)row * D_ + col],       acc[i][j][0], acc[i][j][1]);
            red_add_v2(&C[(size_t)(row + 8) * D_ + col], acc[i][j][2], acc[i][j][3]);
        }
    }
}

// ---------------------------------------------------------------------------
extern "C" void kernel_launch(void* const* d_in, const int* in_sizes, int n_in,
                              void* d_out, int out_size)
{
    const float* query = (const float*)d_in[0];
    const float* key   = (const float*)d_in[1];
    const float* value = (const float*)d_in[2];
    const void*  mask  = d_in[3];
    const float* awb = (const float*)d_in[4];
    const float* Wq = (const float*)d_in[5];
    const float* bq = (const float*)d_in[6];
    const float* Wk = (const float*)d_in[7];
    const float* bk = (const float*)d_in[8];
    const float* Wv = (const float*)d_in[9];
    const float* bv = (const float*)d_in[10];
    const float* Wo = (const float*)d_in[11];
    const float* bo = (const float*)d_in[12];

    float* out = (float*)d_out;                              // (B, L, D)
    float* weights = out + (size_t)B_ * L_ * D_;             // (B, H, L, L)

    float *gq, *gk, *gv, *gattn, *grsum;
    cudaGetSymbolAddress((void**)&gq, g_q);
    cudaGetSymbolAddress((void**)&gk, g_k);
    cudaGetSymbolAddress((void**)&gv, g_v);
    cudaGetSymbolAddress((void**)&gattn, g_attn);
    cudaGetSymbolAddress((void**)&grsum, g_rsum);

    dim3 blk(256);

    // 0) mask dtype sniff + rope table + zero accumulators
    detect_mask_kernel<<<1, 32>>>((const unsigned int*)mask);
    rope_table_kernel<<<(L_ * 32) / 256, 256>>>();
    cudaMemsetAsync(grsum, 0, (size_t)B_ * H_ * L_ * sizeof(float));
    cudaMemsetAsync(gattn, 0, (size_t)ML_ * D_ * sizeof(float));

    // 1) QKV projections via HMMA split-bf16
    dim3 gproj(D_ / 128, ML_ / 128, 3);
    proj_mma<<<gproj, blk>>>(query, key, value, Wq, Wk, Wv,
                             gq, gk, gv, bq, bk, bv);

    // 2) RoPE + split q/k into bf16 planes; V pre-split/transpose
    rope_split_kernel<<<2 * (B_ * L_ * H_ * 32) / 256, 256>>>(gq, gk);
    dim3 gvs(L_ / 64, B_ * H_);
    vsplit_kernel<<<gvs, blk>>>(gv);

    // 3) Logits via HMMA (128x64 tiles, staged epilogue, pre-split Q/K)
    dim3 glog(L_ / 64, L_ / 128, B_ * H_);                   // 32 x 16 x 32
    logits_mma<<<glog, blk>>>(mask, awb, weights);

    // 4) Normalize weights (write back) + attn accumulated via red.v2
    dim3 gat(KSPLIT, L_ / 128, B_ * H_);                     // 8 x 16 x 32
    attnv_mma<<<gat, blk>>>(weights, gattn);

    // 5) Output projection via HMMA
    dim3 gout(D_ / 128, ML_ / 128, 1);
    proj_mma<<<gout, blk>>>(gattn, gattn, gattn, Wo, Wo, Wo,
                            out, out, out, bo, bo, bo);
}